// round 9
// baseline (speedup 1.0000x reference)
#include <cuda_runtime.h>
#include <cuda_bf16.h>
#include <cstdint>

#define ROWSTRIDE 5248
#define NTILES    1312
#define GRIDSZ    148
#define NTHREADS  640
#define SMEM_BYTES 131072

#define BUFSTR 65536u
#define O_ALO  16384u
#define O_BHI  32768u

static __device__ __forceinline__ uint32_t smem_u32(const void* p) {
    uint32_t a;
    asm("{ .reg .u64 t; cvta.to.shared.u64 t, %1; cvt.u32.u64 %0, t; }"
        : "=r"(a) : "l"(p));
    return a;
}
static __device__ __forceinline__ void ldsm4(uint32_t* r, uint32_t a) {
    asm volatile("ldmatrix.sync.aligned.m8n8.x4.shared.b16 {%0,%1,%2,%3}, [%4];"
                 : "=r"(r[0]), "=r"(r[1]), "=r"(r[2]), "=r"(r[3]) : "r"(a));
}
static __device__ __forceinline__ void ldsm4t(uint32_t* r, uint32_t a) {
    asm volatile("ldmatrix.sync.aligned.m8n8.x4.trans.shared.b16 {%0,%1,%2,%3}, [%4];"
                 : "=r"(r[0]), "=r"(r[1]), "=r"(r[2]), "=r"(r[3]) : "r"(a));
}
static __device__ __forceinline__ void mma_bf16(float* c, const uint32_t* a, const uint32_t* b) {
    asm volatile("mma.sync.aligned.m16n8k16.row.col.f32.bf16.bf16.f32 "
                 "{%0,%1,%2,%3}, {%4,%5,%6,%7}, {%8,%9}, {%0,%1,%2,%3};"
                 : "+f"(c[0]), "+f"(c[1]), "+f"(c[2]), "+f"(c[3])
                 : "r"(a[0]), "r"(a[1]), "r"(a[2]), "r"(a[3]), "r"(b[0]), "r"(b[1]));
}
static __device__ __forceinline__ uint32_t hi2(float a, float b, float& ra, float& rb) {
    __nv_bfloat16 ha = __float2bfloat16(a), hb = __float2bfloat16(b);
    ra = a - __bfloat162float(ha);
    rb = b - __bfloat162float(hb);
    return (uint32_t)__bfloat16_as_ushort(ha) | ((uint32_t)__bfloat16_as_ushort(hb) << 16);
}
static __device__ __forceinline__ uint32_t lo2(float a, float b) {
    return (uint32_t)__bfloat16_as_ushort(__float2bfloat16(a)) |
           ((uint32_t)__bfloat16_as_ushort(__float2bfloat16(b)) << 16);
}

__global__ void __launch_bounds__(NTHREADS, 1)
poslin_kernel(const float* __restrict__ x, const float* __restrict__ W,
              const float* __restrict__ bias, float* __restrict__ out)
{
    extern __shared__ __align__(128) char smem[];
    const uint32_t sb = smem_u32(smem);
    const int tid  = threadIdx.x;
    const int lane = tid & 31;
    const int wid  = tid >> 5;                 // 0..19

    const int start = (int)(((long)blockIdx.x * NTILES) / GRIDSZ);
    const int end   = (int)(((long)(blockIdx.x + 1) * NTILES) / GRIDSZ);
    const int Ctot  = (end - start) * 6;

    if (wid >= 16) {
        // ================= PRODUCER (4 warps, 128 threads) =================
        const int ptid = tid - 512;
        const int xq = ptid & 15, xr0 = ptid >> 4;   // x: 16 f4/row, base row 0..7
        const int wq = ptid & 31, wk0 = ptid >> 5;   // W: 32 f4/row, base k 0..3
        const uint32_t xCvt = ((((uint32_t)(xq >> 1)) ^ ((uint32_t)xr0 & 7u)) << 4)
                            + (uint32_t)((xq & 1) << 3);
        // W k&7 alternates with it parity: k = wk0 + 4*it
        const uint32_t wCvt0 = ((((uint32_t)(wq >> 1)) ^ ((uint32_t)wk0 & 7u)) << 4)
                             + (uint32_t)((wq & 1) << 3);
        const uint32_t wCvt1 = ((((uint32_t)(wq >> 1)) ^ (((uint32_t)wk0 + 4u) & 7u)) << 4)
                             + (uint32_t)((wq & 1) << 3);

        int t = start, c = 0;

#define PLOAD(gg) do {                                                          \
    _Pragma("unroll")                                                           \
    for (int it = 0; it < 4; ++it) {                                            \
        const int row_ = xr0 + 32 * (gg) + 8 * it;                              \
        xa[(gg) & 1][it] = v_ ?                                                 \
            *(const float4*)(x + (size_t)(bb_ + row_) * ROWSTRIDE + e_)         \
          : make_float4(0.f, 0.f, 0.f, 0.f);                                    \
        wa[(gg) & 1][it] =                                                      \
            *(const float4*)(Wc_ + (size_t)(wk0 + 16 * (gg) + 4 * it) * 128 + wq * 4); \
    }                                                                           \
} while (0)

#define PSTORE(gg) do {                                                         \
    _Pragma("unroll")                                                           \
    for (int it = 0; it < 4; ++it) {                                            \
        float4 v = xa[(gg) & 1][it];                                            \
        float r0_, r1_, r2_, r3_;                                               \
        uint32_t h0_ = hi2(v.x, v.y, r0_, r1_);                                 \
        uint32_t h1_ = hi2(v.z, v.w, r2_, r3_);                                 \
        uint32_t o_ = bo_ + (uint32_t)(xr0 + 32 * (gg) + 8 * it) * 128u + xCvt; \
        *(uint2*)(smem + o_)         = make_uint2(h0_, h1_);                    \
        *(uint2*)(smem + o_ + O_ALO) = make_uint2(lo2(r0_, r1_), lo2(r2_, r3_));\
        v = wa[(gg) & 1][it];                                                   \
        uint32_t g0_ = hi2(v.x, v.y, r0_, r1_);                                 \
        uint32_t g1_ = hi2(v.z, v.w, r2_, r3_);                                 \
        uint32_t wo_ = bo_ + O_BHI                                              \
                     + (uint32_t)(wk0 + 16 * (gg) + 4 * it) * 256u              \
                     + ((it & 1) ? wCvt1 : wCvt0);                              \
        *(uint2*)(smem + wo_)          = make_uint2(g0_, g1_);                  \
        *(uint2*)(smem + wo_ + 16384u) = make_uint2(lo2(r0_, r1_), lo2(r2_, r3_)); \
    }                                                                           \
} while (0)

#define FILL(bufv) do {                                                         \
    const int s_ = t >> 5, mt_ = t & 31, bb_ = mt_ << 7;                        \
    const int e_ = (s_ - 1) * 128 + c * 64 + xq * 4;                            \
    const bool v_ = (e_ >= 0) && (e_ < ROWSTRIDE);                              \
    const float* Wc_ = W + (size_t)s_ * (384 * 128) + (size_t)(c * 64) * 128;   \
    const uint32_t bo_ = (uint32_t)(bufv) * BUFSTR;                             \
    float4 xa[2][4], wa[2][4];                                                  \
    PLOAD(0);                                                                   \
    PLOAD(1); PSTORE(0);                                                        \
    PLOAD(2); PSTORE(1);                                                        \
    PLOAD(3); PSTORE(2);                                                        \
    PSTORE(3);                                                                  \
} while (0)

        FILL(0);
        for (int g = 0; g < Ctot; ++g) {
            __syncthreads();
            if (g + 1 < Ctot) {
                if (++c == 6) { c = 0; ++t; }
                FILL((g + 1) & 1);
            }
        }
#undef FILL
#undef PLOAD
#undef PSTORE
    } else {
        // ================= CONSUMER (16 warps, 512 threads) =================
        const int m0 = (wid & 3) << 5;
        const int n0 = (wid >> 2) << 5;
        const int g8 = lane >> 2, tig = lane & 3;

        const uint32_t aRowB = (uint32_t)(m0 + (lane & 15));
        const uint32_t aKC   = (uint32_t)(lane >> 4);
        const uint32_t l7    = (uint32_t)(lane & 7);
        const uint32_t bKrB  = (uint32_t)(lane & 15);
        const uint32_t bNCB  = (uint32_t)((n0 >> 3) + (lane >> 4));

        int t = start, c = 0;
        float acc[2][4][4];
        uint32_t ah[2][2][4], al[2][2][4];   // [ks&1][i][4]
        uint32_t bh[2][4], bl[2][4];         // [jj][4]

#define LDA(ks_, ab_) do {                                                      \
    _Pragma("unroll")                                                           \
    for (int i = 0; i < 2; ++i) {                                               \
        uint32_t ad = Ab + (aRowB + 16u * i) * 128u                             \
                    + ((((uint32_t)((ks_) * 2) + aKC) ^ l7) << 4);              \
        ldsm4(ah[ab_][i], ad);                                                  \
        ldsm4(al[ab_][i], ad + O_ALO);                                          \
    }                                                                           \
} while (0)

#define LDB(ks_, jj_, bb_) do {                                                 \
    uint32_t bd = Ab + O_BHI + (bKrB + 16u * (ks_)) * 256u                      \
                + (((bNCB + 2u * (jj_)) ^ l7) << 4);                            \
    ldsm4t(bh[bb_], bd);                                                        \
    ldsm4t(bl[bb_], bd + 16384u);                                               \
} while (0)

#define MMAJ(jj_, ab_, bb_) do {                                                \
    _Pragma("unroll")                                                           \
    for (int i = 0; i < 2; ++i) {                                               \
        mma_bf16(acc[i][2*(jj_)],     ah[ab_][i], bh[bb_]);                     \
        mma_bf16(acc[i][2*(jj_) + 1], ah[ab_][i], bh[bb_] + 2);                 \
        mma_bf16(acc[i][2*(jj_)],     al[ab_][i], bh[bb_]);                     \
        mma_bf16(acc[i][2*(jj_) + 1], al[ab_][i], bh[bb_] + 2);                 \
        mma_bf16(acc[i][2*(jj_)],     ah[ab_][i], bl[bb_]);                     \
        mma_bf16(acc[i][2*(jj_) + 1], ah[ab_][i], bl[bb_] + 2);                 \
    }                                                                           \
} while (0)

        for (int g = 0; g < Ctot; ++g) {
            __syncthreads();
            if (c == 0) {
                _Pragma("unroll")
                for (int i = 0; i < 2; ++i)
                    _Pragma("unroll")
                    for (int j = 0; j < 4; ++j)
                        _Pragma("unroll")
                        for (int u = 0; u < 4; ++u) acc[i][j][u] = 0.f;
            }
            {
                const uint32_t Ab = sb + (uint32_t)(g & 1) * BUFSTR;
                LDA(0, 0);
                LDB(0, 0, 0);
                _Pragma("unroll")
                for (int ks = 0; ks < 4; ++ks) {
                    const int ab = ks & 1;
                    LDB(ks, 1, 1);                       // B jj=1 ahead of use
                    MMAJ(0, ab, 0);                      // 12 mma cover it
                    if (ks < 3) {
                        LDA(ks + 1, ab ^ 1);             // next A into alt buf
                        LDB(ks + 1, 0, 0);               // next B jj=0
                    }
                    MMAJ(1, ab, 1);                      // 12 mma cover them
                }
            }
            if (c == 5) {
                const int s = t >> 5, bbase = (t & 31) << 7;
                const float* brow = bias + s * 128;
                _Pragma("unroll")
                for (int j = 0; j < 4; ++j) {
                    const int n = n0 + 8 * j + 2 * tig;
                    const float b0 = brow[n], b1 = brow[n + 1];
                    _Pragma("unroll")
                    for (int i = 0; i < 2; ++i) {
                        const size_t rb = (size_t)(bbase + m0 + 16 * i + g8) * ROWSTRIDE
                                        + (size_t)s * 128 + n;
                        float2 v0, v1;
                        v0.x = fmaxf(acc[i][j][0] + b0, 0.f);
                        v0.y = fmaxf(acc[i][j][1] + b1, 0.f);
                        v1.x = fmaxf(acc[i][j][2] + b0, 0.f);
                        v1.y = fmaxf(acc[i][j][3] + b1, 0.f);
                        *(float2*)(out + rb)                 = v0;
                        *(float2*)(out + rb + 8 * ROWSTRIDE) = v1;
                    }
                }
            }
            if (++c == 6) { c = 0; ++t; }
        }
#undef LDA
#undef LDB
#undef MMAJ
    }
}

extern "C" void kernel_launch(void* const* d_in, const int* in_sizes, int n_in,
                              void* d_out, int out_size) {
    const float* x = (const float*)d_in[0];
    const float* W = (const float*)d_in[1];
    const float* b = (const float*)d_in[2];
    float* out = (float*)d_out;
    cudaFuncSetAttribute(poslin_kernel,
                         cudaFuncAttributeMaxDynamicSharedMemorySize, SMEM_BYTES);
    poslin_kernel<<<GRIDSZ, NTHREADS, SMEM_BYTES>>>(x, W, b, out);
}

// round 10
// speedup vs baseline: 1.8896x; 1.8896x over previous
#include <cuda_runtime.h>
#include <cuda_bf16.h>
#include <cstdint>

#define ROWSTRIDE 5248
#define NTILES    1312
#define GRIDSZ    148
#define NTHREADS  768
#define SMEM_BYTES 131072

#define BUFSTR 65536u
#define O_ALO  16384u
#define O_BHI  32768u

static __device__ __forceinline__ uint32_t smem_u32(const void* p) {
    uint32_t a;
    asm("{ .reg .u64 t; cvta.to.shared.u64 t, %1; cvt.u32.u64 %0, t; }"
        : "=r"(a) : "l"(p));
    return a;
}
static __device__ __forceinline__ void ldsm4(uint32_t* r, uint32_t a) {
    asm volatile("ldmatrix.sync.aligned.m8n8.x4.shared.b16 {%0,%1,%2,%3}, [%4];"
                 : "=r"(r[0]), "=r"(r[1]), "=r"(r[2]), "=r"(r[3]) : "r"(a));
}
static __device__ __forceinline__ void ldsm4t(uint32_t* r, uint32_t a) {
    asm volatile("ldmatrix.sync.aligned.m8n8.x4.trans.shared.b16 {%0,%1,%2,%3}, [%4];"
                 : "=r"(r[0]), "=r"(r[1]), "=r"(r[2]), "=r"(r[3]) : "r"(a));
}
static __device__ __forceinline__ void mma_bf16(float* c, const uint32_t* a, const uint32_t* b) {
    asm volatile("mma.sync.aligned.m16n8k16.row.col.f32.bf16.bf16.f32 "
                 "{%0,%1,%2,%3}, {%4,%5,%6,%7}, {%8,%9}, {%0,%1,%2,%3};"
                 : "+f"(c[0]), "+f"(c[1]), "+f"(c[2]), "+f"(c[3])
                 : "r"(a[0]), "r"(a[1]), "r"(a[2]), "r"(a[3]), "r"(b[0]), "r"(b[1]));
}
static __device__ __forceinline__ uint32_t hi2(float a, float b, float& ra, float& rb) {
    __nv_bfloat16 ha = __float2bfloat16(a), hb = __float2bfloat16(b);
    ra = a - __bfloat162float(ha);
    rb = b - __bfloat162float(hb);
    return (uint32_t)__bfloat16_as_ushort(ha) | ((uint32_t)__bfloat16_as_ushort(hb) << 16);
}
static __device__ __forceinline__ uint32_t lo2(float a, float b) {
    return (uint32_t)__bfloat16_as_ushort(__float2bfloat16(a)) |
           ((uint32_t)__bfloat16_as_ushort(__float2bfloat16(b)) << 16);
}

__global__ void __launch_bounds__(NTHREADS, 1)
poslin_kernel(const float* __restrict__ x, const float* __restrict__ W,
              const float* __restrict__ bias, float* __restrict__ out)
{
    extern __shared__ __align__(128) char smem[];
    const uint32_t sb = smem_u32(smem);
    const int tid  = threadIdx.x;
    const int lane = tid & 31;
    const int wid  = tid >> 5;                 // 0..23

    const int start = (int)(((long)blockIdx.x * NTILES) / GRIDSZ);
    const int end   = (int)(((long)(blockIdx.x + 1) * NTILES) / GRIDSZ);
    const int Ctot  = (end - start) * 6;

    if (wid >= 16) {
        // ============ PRODUCER (8 warps): LDG one chunk ahead of STS ========
        const int ptid = tid - 512;
        const int xq = ptid & 15, xr0 = ptid >> 4;   // x: float4-in-row, row base
        const int wq = ptid & 31, wk0 = ptid >> 5;   // W: float4-in-row, k base
        const uint32_t xCvt = ((((uint32_t)(xq >> 1)) ^ ((uint32_t)xr0 & 7u)) << 4)
                            + (uint32_t)((xq & 1) << 3);
        const uint32_t wCvt = ((((uint32_t)(wq >> 1)) ^ ((uint32_t)wk0 & 7u)) << 4)
                            + (uint32_t)((wq & 1) << 3);

        float4 xa[8], wa[8];       // chunk held in regs across one iteration
        int tL = start, cL = 0;    // chunk currently targeted by LDGC

#define LDGC() do {                                                             \
    const int s_ = tL >> 5, mt_ = tL & 31, bb_ = mt_ << 7;                      \
    const int e_ = (s_ - 1) * 128 + cL * 64 + xq * 4;                           \
    const bool v_ = (e_ >= 0) && (e_ < ROWSTRIDE);                              \
    const float* Wc_ = W + (size_t)s_ * (384 * 128) + (size_t)(cL * 64) * 128;  \
    _Pragma("unroll")                                                           \
    for (int it = 0; it < 8; ++it)                                              \
        xa[it] = v_ ? *(const float4*)(x + (size_t)(bb_ + xr0 + 16*it) * ROWSTRIDE + e_) \
                    : make_float4(0.f, 0.f, 0.f, 0.f);                          \
    _Pragma("unroll")                                                           \
    for (int it = 0; it < 8; ++it)                                              \
        wa[it] = *(const float4*)(Wc_ + (size_t)(wk0 + 8*it) * 128 + wq * 4);   \
} while (0)

#define STSC(bufv) do {                                                         \
    const uint32_t bo_ = (uint32_t)(bufv) * BUFSTR;                             \
    _Pragma("unroll")                                                           \
    for (int it = 0; it < 8; ++it) {                                            \
        float r0_, r1_, r2_, r3_;                                               \
        uint32_t h0_ = hi2(xa[it].x, xa[it].y, r0_, r1_);                       \
        uint32_t h1_ = hi2(xa[it].z, xa[it].w, r2_, r3_);                       \
        uint32_t o_ = bo_ + (uint32_t)(xr0 + 16*it) * 128u + xCvt;              \
        *(uint2*)(smem + o_)         = make_uint2(h0_, h1_);                    \
        *(uint2*)(smem + o_ + O_ALO) = make_uint2(lo2(r0_, r1_), lo2(r2_, r3_));\
    }                                                                           \
    _Pragma("unroll")                                                           \
    for (int it = 0; it < 8; ++it) {                                            \
        float r0_, r1_, r2_, r3_;                                               \
        uint32_t h0_ = hi2(wa[it].x, wa[it].y, r0_, r1_);                       \
        uint32_t h1_ = hi2(wa[it].z, wa[it].w, r2_, r3_);                       \
        uint32_t o_ = bo_ + O_BHI + (uint32_t)(wk0 + 8*it) * 256u + wCvt;       \
        *(uint2*)(smem + o_)          = make_uint2(h0_, h1_);                   \
        *(uint2*)(smem + o_ + 16384u) = make_uint2(lo2(r0_, r1_), lo2(r2_, r3_)); \
    }                                                                           \
} while (0)

        LDGC();                                   // chunk 0 -> regs
        STSC(0);                                  // chunk 0 -> buf 0
        if (++cL == 6) { cL = 0; ++tL; }
        if (Ctot > 1) LDGC();                     // chunk 1 -> regs

        for (int g = 0; g < Ctot; ++g) {
            __syncthreads();
            if (g + 1 < Ctot) {
                STSC((g + 1) & 1);                // regs (chunk g+1) -> smem
                if (++cL == 6) { cL = 0; ++tL; }
                if (g + 2 < Ctot) LDGC();         // chunk g+2 -> regs (lands next iter)
            }
        }
#undef LDGC
#undef STSC
    } else {
        // ================= CONSUMER (16 warps, 512 threads) =================
        const int m0 = (wid & 3) << 5;
        const int n0 = (wid >> 2) << 5;
        const int g8 = lane >> 2, tig = lane & 3;

        const uint32_t aRowB = (uint32_t)(m0 + (lane & 15));
        const uint32_t aKC   = (uint32_t)(lane >> 4);
        const uint32_t l7    = (uint32_t)(lane & 7);
        const uint32_t bKrB  = (uint32_t)(lane & 15);
        const uint32_t bNCB  = (uint32_t)((n0 >> 3) + (lane >> 4));

        int t = start, c = 0;
        float acc[2][4][4];

        for (int g = 0; g < Ctot; ++g) {
            __syncthreads();
            if (c == 0) {
                _Pragma("unroll")
                for (int i = 0; i < 2; ++i)
                    _Pragma("unroll")
                    for (int j = 0; j < 4; ++j)
                        _Pragma("unroll")
                        for (int u = 0; u < 4; ++u) acc[i][j][u] = 0.f;
            }
            {
                const uint32_t Ab = sb + (uint32_t)(g & 1) * BUFSTR;
                _Pragma("unroll")
                for (int ks = 0; ks < 4; ++ks) {
                    uint32_t ah[2][4], al[2][4];
                    _Pragma("unroll")
                    for (int i = 0; i < 2; ++i) {
                        uint32_t ad = Ab + (aRowB + 16u*i) * 128u
                                    + ((((uint32_t)(ks * 2) + aKC) ^ l7) << 4);
                        ldsm4(ah[i], ad);
                        ldsm4(al[i], ad + O_ALO);
                    }
                    _Pragma("unroll")
                    for (int jj = 0; jj < 2; ++jj) {
                        uint32_t bd = Ab + O_BHI + (bKrB + 16u*ks) * 256u
                                    + (((bNCB + 2u*jj) ^ l7) << 4);
                        uint32_t bh_[4], bl_[4];
                        ldsm4t(bh_, bd);
                        ldsm4t(bl_, bd + 16384u);    // hoisted: covered by bh MMAs
                        _Pragma("unroll")
                        for (int i = 0; i < 2; ++i) {
                            mma_bf16(acc[i][2*jj],     ah[i], bh_);
                            mma_bf16(acc[i][2*jj + 1], ah[i], bh_ + 2);
                            mma_bf16(acc[i][2*jj],     al[i], bh_);
                            mma_bf16(acc[i][2*jj + 1], al[i], bh_ + 2);
                        }
                        _Pragma("unroll")
                        for (int i = 0; i < 2; ++i) {
                            mma_bf16(acc[i][2*jj],     ah[i], bl_);
                            mma_bf16(acc[i][2*jj + 1], ah[i], bl_ + 2);
                        }
                    }
                }
            }
            if (c == 5) {
                const int s = t >> 5, bbase = (t & 31) << 7;
                const float* brow = bias + s * 128;
                _Pragma("unroll")
                for (int j = 0; j < 4; ++j) {
                    const int n = n0 + 8 * j + 2 * tig;
                    const float b0 = brow[n], b1 = brow[n + 1];
                    _Pragma("unroll")
                    for (int i = 0; i < 2; ++i) {
                        const size_t rb = (size_t)(bbase + m0 + 16 * i + g8) * ROWSTRIDE
                                        + (size_t)s * 128 + n;
                        float2 v0, v1;
                        v0.x = fmaxf(acc[i][j][0] + b0, 0.f);
                        v0.y = fmaxf(acc[i][j][1] + b1, 0.f);
                        v1.x = fmaxf(acc[i][j][2] + b0, 0.f);
                        v1.y = fmaxf(acc[i][j][3] + b1, 0.f);
                        *(float2*)(out + rb)                 = v0;
                        *(float2*)(out + rb + 8 * ROWSTRIDE) = v1;
                    }
                }
            }
            if (++c == 6) { c = 0; ++t; }
        }
    }
}

extern "C" void kernel_launch(void* const* d_in, const int* in_sizes, int n_in,
                              void* d_out, int out_size) {
    const float* x = (const float*)d_in[0];
    const float* W = (const float*)d_in[1];
    const float* b = (const float*)d_in[2];
    float* out = (float*)d_out;
    cudaFuncSetAttribute(poslin_kernel,
                         cudaFuncAttributeMaxDynamicSharedMemorySize, SMEM_BYTES);
    poslin_kernel<<<GRIDSZ, NTHREADS, SMEM_BYTES>>>(x, W, b, out);
}